// round 11
// baseline (speedup 1.0000x reference)
#include <cuda_runtime.h>
#include <cuda_bf16.h>
#include <math.h>
#include <stdint.h>

// ===================== asm helpers =====================
__device__ __forceinline__ uint32_t smem_u32(const void* p) {
    uint32_t a;
    asm("{ .reg .u64 t; cvta.to.shared.u64 t, %1; cvt.u32.u64 %0, t; }" : "=r"(a) : "l"(p));
    return a;
}
#define CP16(dst_u32, src_ptr) \
    asm volatile("cp.async.cg.shared.global [%0], [%1], 16;" :: "r"(dst_u32), "l"(src_ptr) : "memory")
#define CP_COMMIT() asm volatile("cp.async.commit_group;" ::: "memory")
#define CP_WAIT(n)  asm volatile("cp.async.wait_group %0;" :: "n"(n) : "memory")

#define MMA(d, a0, a1, a2, a3, b0, b1) \
    asm("mma.sync.aligned.m16n8k16.row.col.f32.bf16.bf16.f32 " \
        "{%0,%1,%2,%3}, {%4,%5,%6,%7}, {%8,%9}, {%0,%1,%2,%3};" \
        : "+f"((d)[0]), "+f"((d)[1]), "+f"((d)[2]), "+f"((d)[3]) \
        : "r"(a0), "r"(a1), "r"(a2), "r"(a3), "r"(b0), "r"(b1))

// ===================== smem layout =====================
#define SM_P2    0          // 131072   W2 fragments (uint4-paired)
#define SM_P3    131072     // 8192     W3 fragments
#define SM_H1F   139264     // 65536    H1 A-fragments [16kt][4mt][2rb][32][4]u32 (phase 2)
#define SM_P1    139264     //   phase-1 alias: W1 fragments (32768)
#define SM_XF    172032     //   phase-1 alias: X A-fragments [4kt][4mt][2rb][32][4]u32 (16384)
#define SM_B1    204800     // 1024
#define SM_B2    205824     // 1024
#define SM_B3    206848     // 64
#define SM_DIR   206912     // 128
#define SM_COMP  207040     // 2048
#define SM_BC2   209088     // 16
#define SM_WC1   209104     // 10752  (resident whole kernel now)
#define SM_WC2   219856     // 768
#define SM_BC1   220624     // 256
#define SMEM_BYTES 220880
// aliases inside dead P2 region (valid after layer-2 MMAs):
#define SM_RED   0          // 71680  (7 x 128 x 20 fp32) layer-3 partials
#define SM_DIRC  71680      // 256    dircontrib[64]
#define SM_CPART 71936      // 14336  (7 groups x 128 x 4 floats)
#define SM_GEOS  86272      // 8448   [16][132] fp32 (transposed)

// packed weight image (bf16 fragment order, uint4-paired): P1 32KB | P2 128KB | P3 8KB
__device__ __align__(128) uint32_t g_pack[43008];

__device__ __forceinline__ uint32_t bf16_pack2(float x, float y) {
    __nv_bfloat16 hx = __float2bfloat16(x), hy = __float2bfloat16(y);
    return (uint32_t)__bfloat16_as_ushort(hx) | ((uint32_t)__bfloat16_as_ushort(hy) << 16);
}
__device__ __forceinline__ void sts_bf16(uint32_t addr, float v) {
    uint16_t u = __bfloat16_as_ushort(__float2bfloat16(v));
    asm volatile("st.shared.u16 [%0], %1;" :: "r"(addr), "h"(u));
}
// Cody-Waite reduce to [-pi,pi], then MUFU sin/cos (abs err ~2^-20, far below the
// bf16 quantization these values immediately undergo).
__device__ __forceinline__ void sincos_fast(float phi, float* s, float* c) {
    float k = rintf(phi * 0.15915494309f);
    float r = fmaf(-k, 6.2831854820251465f, phi);
    r = fmaf(-k, -1.7484556000744263e-07f, r);
    *s = __sinf(r);
    *c = __cosf(r);
}

// byte address (relative) of feature j of sample m inside an A-fragment array
__device__ __forceinline__ uint32_t xf_addr(int m, int j) {
    int p = j >> 1;
    int kt = p >> 3;
    int mtx = m >> 5;
    int lm = m & 31;
    int rb = lm >> 4;
    int l16 = lm & 15;
    int rowbit = l16 >> 3;
    int lane = (l16 & 7) * 4 + (p & 3);
    int jj = ((p >> 2) & 1) * 2 + rowbit;
    return (uint32_t)(((((kt * 4 + mtx) * 2 + rb) * 32 + lane) * 4 + jj) * 4 + (j & 1) * 2);
}

// ===================== prep: pack weights, N-tile pairs per uint4 =====================
// (accurate bf16 conversion; runs once)
__device__ __forceinline__ void sincos_acc_prep(float phi, float* s, float* c) {
    float k = rintf(phi * 0.15915494309f);
    float r = fmaf(-k, 6.2831854820251465f, phi);
    r = fmaf(-k, -1.7484556000744263e-07f, r);
    sincosf(r, s, c);
}
__global__ void prep_pack(const float* __restrict__ W1, const float* __restrict__ W2,
                          const float* __restrict__ W3) {
    int s = blockIdx.x * 256 + threadIdx.x;
    if (s >= 21504) return;
    int lane = s & 31;
    int qn = lane >> 2, qk = (lane & 3) * 2;
    const float* W; int kbase, n, ldn, kmax; uint32_t base, idx;
    if (s < 4096) {                       // P1: 4 kt x 32 nt
        int t = s >> 5;
        int kt = t >> 5, nt = t & 31;
        kbase = kt * 16; n = nt * 8 + qn; W = W1; ldn = 256; kmax = 63;
        base = 0; idx = (uint32_t)(((kt * 16 + (nt >> 1)) * 32 + lane) * 4 + (nt & 1) * 2);
    } else if (s < 20480) {               // P2: 16 kt x 32 nt
        int t = (s - 4096) >> 5;
        int kt = t >> 5, nt = t & 31;
        kbase = kt * 16; n = nt * 8 + qn; W = W2; ldn = 256; kmax = 256;
        base = 8192; idx = (uint32_t)(((kt * 16 + (nt >> 1)) * 32 + lane) * 4 + (nt & 1) * 2);
    } else {                              // P3: 16 kt x 2 nt
        int t = (s - 20480) >> 5;
        int kt = t >> 1, nt = t & 1;
        kbase = kt * 16; n = nt * 8 + qn; W = W3; ldn = 16; kmax = 256;
        base = 40960; idx = (uint32_t)((kt * 32 + lane) * 4 + nt * 2);
    }
    int k0 = kbase + qk;
    float e0 = (k0     < kmax) ? W[(k0)     * ldn + n] : 0.f;
    float e1 = (k0 + 1 < kmax) ? W[(k0 + 1) * ldn + n] : 0.f;
    float e2 = (k0 + 8 < kmax) ? W[(k0 + 8) * ldn + n] : 0.f;
    float e3 = (k0 + 9 < kmax) ? W[(k0 + 9) * ldn + n] : 0.f;
    g_pack[base + idx]     = bf16_pack2(e0, e1);
    g_pack[base + idx + 1] = bf16_pack2(e2, e3);
}

// ===================== main kernel: 1024 threads, 32 warps =====================
__global__ void __launch_bounds__(1024, 1)
nerf_mma(const float* __restrict__ rays_o, const float* __restrict__ rays_d,
         const float* __restrict__ b1, const float* __restrict__ b2,
         const float* __restrict__ b3,
         const float* __restrict__ Wc1, const float* __restrict__ bc1,
         const float* __restrict__ Wc2, const float* __restrict__ bc2,
         float* __restrict__ out)
{
    extern __shared__ char smem[];
    const int tid  = threadIdx.x;
    const int lane = tid & 31;
    const int w    = tid >> 5;
    const int mt   = w & 3;               // M-tile (32 rows)
    const int nq   = w >> 2;              // N-eighth (32 cols)
    const int la3  = lane & 3;
    const int qk   = la3 * 2;
    const int r0   = mt * 32 + (lane >> 2);
    const int ray  = blockIdx.x;

    const uint32_t sb = smem_u32(smem);
    float* b1s  = (float*)(smem + SM_B1);
    float* b2s  = (float*)(smem + SM_B2);
    float* b3s  = (float*)(smem + SM_B3);
    float* dirs = (float*)(smem + SM_DIR);
    float* comp = (float*)(smem + SM_COMP);
    float* bc2s = (float*)(smem + SM_BC2);
    const uint4* P1q = (const uint4*)(smem + SM_P1);
    const uint4* P2q = (const uint4*)(smem + SM_P2);
    const uint4* P3q = (const uint4*)(smem + SM_P3);
    const char* gp = (const char*)g_pack;

    // ---- async staging: P1 (g1), P2 (g2), P3+color weights (g3) ----
    {
        uint32_t d1 = sb + SM_P1, d2 = sb + SM_P2, d3 = sb + SM_P3;
        #pragma unroll
        for (int j = 0; j < 2; j++)
            CP16(d1 + (uint32_t)(tid + j * 1024) * 16, gp + (tid + j * 1024) * 16);
        CP_COMMIT();
        #pragma unroll
        for (int j = 0; j < 8; j++)
            CP16(d2 + (uint32_t)(tid + j * 1024) * 16, gp + 32768 + (tid + j * 1024) * 16);
        CP_COMMIT();
        if (tid < 512) CP16(d3 + (uint32_t)tid * 16, gp + 163840 + tid * 16);
        if (tid < 672) CP16(sb + SM_WC1 + (uint32_t)tid*16, (const char*)Wc1 + tid*16);
        if (tid < 48)  CP16(sb + SM_WC2 + (uint32_t)tid*16, (const char*)Wc2 + tid*16);
        if (tid < 16)  CP16(sb + SM_BC1 + (uint32_t)tid*16, (const char*)bc1 + tid*16);
        CP_COMMIT();
    }

    // ---- small constants ----
    if (tid < 256) { b1s[tid] = b1[tid]; b2s[tid] = b2[tid]; }
    if (tid < 16) b3s[tid] = b3[tid];
    if (tid < 3)  bc2s[tid] = bc2[tid];

    // ---- ray setup (redundant, all threads; fast math) ----
    float ox = rays_o[ray*3+0], oy = rays_o[ray*3+1], oz = rays_o[ray*3+2];
    float rdx = rays_d[ray*3+0], rdy = rays_d[ray*3+1], rdz = rays_d[ray*3+2];
    float inv_norm = rsqrtf(rdx*rdx + rdy*rdy + rdz*rdz);
    float dx = rdx*inv_norm, dy = rdy*inv_norm, dz = rdz*inv_norm;
    float near_t, far_t;
    {
        float dd;
        dd = (fabsf(dx) < 1e-8f) ? 1e-8f : dx; float i0 = __fdividef(1.0f, dd);
        dd = (fabsf(dy) < 1e-8f) ? 1e-8f : dy; float i1 = __fdividef(1.0f, dd);
        dd = (fabsf(dz) < 1e-8f) ? 1e-8f : dz; float i2 = __fdividef(1.0f, dd);
        float t0x=(-1.f-ox)*i0, t1x=(1.f-ox)*i0;
        float t0y=(-1.f-oy)*i1, t1y=(1.f-oy)*i1;
        float t0z=(-1.f-oz)*i2, t1z=(1.f-oz)*i2;
        float nx=fminf(t0x,t1x), fx=fmaxf(t0x,t1x);
        float ny=fminf(t0y,t1y), fy=fmaxf(t0y,t1y);
        float nz=fminf(t0z,t1z), fz=fmaxf(t0z,t1z);
        near_t = fmaxf(fmaxf(nx, fmaxf(ny, nz)), 0.02f);
        far_t  = fminf(fmaxf(fx, fmaxf(fy, fz)), 1000.f);
        far_t  = fmaxf(far_t, near_t + 0.001f);
    }
    const float dtv = (far_t - near_t) * (1.0f/128.0f);

    // ---- posenc (8-way split over groups g = tid>>7), writes A-fragment layout --
    {
        const int m = tid & 127, g = tid >> 7;
        float t = near_t + ((float)m + 0.5f) * dtv;
        float px = ox + t*dx, py = oy + t*dy, pz = oz + t*dz;
        const uint32_t xbase = sb + SM_XF;
        if (g < 6) {
            int ci = g >> 1, half = g & 1;
            float pv = (ci == 0) ? px : ((ci == 1) ? py : pz);
            float f = half ? 32.f : 1.f;
            #pragma unroll
            for (int q = 0; q < 5; q++) {
                int qq = half*5 + q;
                float s, c;
                sincos_fast(pv * f, &s, &c);
                sts_bf16(xbase + xf_addr(m, 3 + ci*10 + qq), s);
                sts_bf16(xbase + xf_addr(m, 33 + ci*10 + qq), c);
                f *= 2.f;
            }
        } else if (g == 6) {
            sts_bf16(xbase + xf_addr(m, 0), px);
            sts_bf16(xbase + xf_addr(m, 1), py);
            sts_bf16(xbase + xf_addr(m, 2), pz);
            sts_bf16(xbase + xf_addr(m, 63), 0.f);
        } else {
            if (m < 27) {
                int j = m;
                float dv[3] = {dx, dy, dz};
                float v;
                if (j < 3) v = dv[j];
                else if (j < 15) { int jj = j-3;  float s,c; sincos_fast(dv[jj>>2]*(float)(1<<(jj&3)), &s, &c); v = s; }
                else             { int jj = j-15; float s,c; sincos_fast(dv[jj>>2]*(float)(1<<(jj&3)), &s, &c); v = c; }
                dirs[j] = v;
            }
        }
    }

    CP_WAIT(2);            // P1 landed
    __syncthreads();

    // ---------------- Layer 1: warp = 32 rows x 32 cols ----------------
    float acc[2][4][4];
    #pragma unroll
    for (int rb = 0; rb < 2; rb++)
        #pragma unroll
        for (int ct = 0; ct < 4; ct++)
            #pragma unroll
            for (int j = 0; j < 4; j++) acc[rb][ct][j] = 0.f;

    {
        const uint4* pA = (const uint4*)(smem + SM_XF) + mt*64 + lane;
        #pragma unroll
        for (int kt = 0; kt < 4; kt++) {
            uint4 a0 = pA[kt*256];
            uint4 a1 = pA[kt*256 + 32];
            uint4 p0 = P1q[(kt*16 + nq*2)*32 + lane];
            uint4 p1 = P1q[(kt*16 + nq*2 + 1)*32 + lane];
            MMA(acc[0][0], a0.x, a0.y, a0.z, a0.w, p0.x, p0.y);
            MMA(acc[0][1], a0.x, a0.y, a0.z, a0.w, p0.z, p0.w);
            MMA(acc[0][2], a0.x, a0.y, a0.z, a0.w, p1.x, p1.y);
            MMA(acc[0][3], a0.x, a0.y, a0.z, a0.w, p1.z, p1.w);
            MMA(acc[1][0], a1.x, a1.y, a1.z, a1.w, p0.x, p0.y);
            MMA(acc[1][1], a1.x, a1.y, a1.z, a1.w, p0.z, p0.w);
            MMA(acc[1][2], a1.x, a1.y, a1.z, a1.w, p1.x, p1.y);
            MMA(acc[1][3], a1.x, a1.y, a1.z, a1.w, p1.z, p1.w);
        }
    }
    __syncthreads();       // everyone done reading XF / P1

    // epilogue: H1 = relu(acc + b1) -> A-fragment layout (overwrites P1/XF region)
    #pragma unroll
    for (int ct = 0; ct < 4; ct++) {
        int n0 = nq*32 + ct*8 + qk;
        float2 bb = *(const float2*)(b1s + n0);
        int kt = nq*2 + (ct >> 1);
        int j0 = (ct & 1) * 2;
        #pragma unroll
        for (int rb = 0; rb < 2; rb++) {
            uint32_t v0 = bf16_pack2(fmaxf(acc[rb][ct][0] + bb.x, 0.f), fmaxf(acc[rb][ct][1] + bb.y, 0.f));
            uint32_t v1 = bf16_pack2(fmaxf(acc[rb][ct][2] + bb.x, 0.f), fmaxf(acc[rb][ct][3] + bb.y, 0.f));
            uint32_t idx = (uint32_t)((((kt*4 + mt)*2 + rb)*32 + lane)*4 + j0);
            *(uint2*)(smem + SM_H1F + idx*4) = make_uint2(v0, v1);
        }
    }
    CP_WAIT(0);            // P2 + P3 + color weights landed (hidden behind L1+epilogue)
    __syncthreads();

    // ---------------- Layer 2: 16 K-tiles ----------------
    #pragma unroll
    for (int rb = 0; rb < 2; rb++)
        #pragma unroll
        for (int ct = 0; ct < 4; ct++)
            #pragma unroll
            for (int j = 0; j < 4; j++) acc[rb][ct][j] = 0.f;

    {
        const uint4* pA = (const uint4*)(smem + SM_H1F) + mt*64 + lane;
        #pragma unroll
        for (int kt = 0; kt < 16; kt++) {
            uint4 a0 = pA[kt*256];
            uint4 a1 = pA[kt*256 + 32];
            uint4 p0 = P2q[(kt*16 + nq*2)*32 + lane];
            uint4 p1 = P2q[(kt*16 + nq*2 + 1)*32 + lane];
            MMA(acc[0][0], a0.x, a0.y, a0.z, a0.w, p0.x, p0.y);
            MMA(acc[0][1], a0.x, a0.y, a0.z, a0.w, p0.z, p0.w);
            MMA(acc[0][2], a0.x, a0.y, a0.z, a0.w, p1.x, p1.y);
            MMA(acc[0][3], a0.x, a0.y, a0.z, a0.w, p1.z, p1.w);
            MMA(acc[1][0], a1.x, a1.y, a1.z, a1.w, p0.x, p0.y);
            MMA(acc[1][1], a1.x, a1.y, a1.z, a1.w, p0.z, p0.w);
            MMA(acc[1][2], a1.x, a1.y, a1.z, a1.w, p1.x, p1.y);
            MMA(acc[1][3], a1.x, a1.y, a1.z, a1.w, p1.z, p1.w);
        }
    }
    __syncthreads();       // everyone done reading P2 (RED may now alias it)

    // ---------------- Layer 3: warp owns K-range nq*32..+32 of its 32 rows ------
    float geo[2][2][4];    // [rb][nt]
    #pragma unroll
    for (int rb = 0; rb < 2; rb++)
        #pragma unroll
        for (int nt = 0; nt < 2; nt++)
            #pragma unroll
            for (int j = 0; j < 4; j++) geo[rb][nt][j] = 0.f;

    #pragma unroll
    for (int ii = 0; ii < 2; ii++) {
        int kt3 = nq*2 + ii;
        uint4 bq = P3q[kt3*32 + lane];
        int n0 = nq*32 + (2*ii)*8 + qk;
        float2 bb0 = *(const float2*)(b2s + n0);
        float2 bb1 = *(const float2*)(b2s + n0 + 8);
        #pragma unroll
        for (int rb = 0; rb < 2; rb++) {
            uint32_t a0 = bf16_pack2(fmaxf(acc[rb][2*ii][0] + bb0.x, 0.f),  fmaxf(acc[rb][2*ii][1] + bb0.y, 0.f));
            uint32_t a1 = bf16_pack2(fmaxf(acc[rb][2*ii][2] + bb0.x, 0.f),  fmaxf(acc[rb][2*ii][3] + bb0.y, 0.f));
            uint32_t a2 = bf16_pack2(fmaxf(acc[rb][2*ii+1][0] + bb1.x, 0.f), fmaxf(acc[rb][2*ii+1][1] + bb1.y, 0.f));
            uint32_t a3 = bf16_pack2(fmaxf(acc[rb][2*ii+1][2] + bb1.x, 0.f), fmaxf(acc[rb][2*ii+1][3] + bb1.y, 0.f));
            MMA(geo[rb][0], a0, a1, a2, a3, bq.x, bq.y);
            MMA(geo[rb][1], a0, a1, a2, a3, bq.z, bq.w);
        }
    }

    // 8-way K reduction via SMEM (dead P2 region, stride 20 pad)
    if (nq > 0) {
        float* red = (float*)(smem + SM_RED) + (nq - 1) * 2560;
        #pragma unroll
        for (int rb = 0; rb < 2; rb++)
            #pragma unroll
            for (int nt = 0; nt < 2; nt++) {
                int c = nt*8 + qk;
                int rr = r0 + rb*16;
                red[rr*20 + c]       = geo[rb][nt][0];
                red[rr*20 + c + 1]   = geo[rb][nt][1];
                red[(rr+8)*20 + c]   = geo[rb][nt][2];
                red[(rr+8)*20 + c+1] = geo[rb][nt][3];
            }
    }
    __syncthreads();
    if (nq == 0) {
        const float* red = (const float*)(smem + SM_RED);
        float* geos = (float*)(smem + SM_GEOS);   // transposed [16][132]
        #pragma unroll
        for (int rb = 0; rb < 2; rb++)
            #pragma unroll
            for (int nt = 0; nt < 2; nt++) {
                int c = nt*8 + qk;
                #pragma unroll
                for (int hv = 0; hv < 2; hv++) {
                    int rr = r0 + rb*16 + hv*8;
                    float v0 = geo[rb][nt][2*hv+0];
                    float v1 = geo[rb][nt][2*hv+1];
                    #pragma unroll
                    for (int gg = 0; gg < 7; gg++) {
                        v0 += red[gg*2560 + rr*20 + c];
                        v1 += red[gg*2560 + rr*20 + c + 1];
                    }
                    geos[c*132 + rr]     = v0;
                    geos[(c+1)*132 + rr] = v1;
                }
            }
    }
    __syncthreads();

    // ---------------- color head ----------------
    {
        const float* wc1s = (const float*)(smem + SM_WC1);
        const float* wc2s = (const float*)(smem + SM_WC2);
        const float* bc1s = (const float*)(smem + SM_BC1);
        const float* geos = (const float*)(smem + SM_GEOS);
        float* dc   = (float*)(smem + SM_DIRC);
        float* cpart= (float*)(smem + SM_CPART);

        // phase A: dircontrib[j] (ray-constant), 64 threads
        if (tid < 64) {
            int j = tid;
            float h = bc1s[j];
            #pragma unroll
            for (int i = 0; i < 27; i++)
                h = fmaf(dirs[i], wc1s[i*64 + j], h);
            dc[j] = h;
        }
        __syncthreads();

        // phase B: 8 groups x 8 j's; fea[15] in regs
        const int m = tid & 127, g = tid >> 7;
        float fea[15];
        #pragma unroll
        for (int i = 0; i < 15; i++) fea[i] = geos[(1+i)*132 + m] + b3s[1+i];
        float a0 = 0.f, a1 = 0.f, a2 = 0.f;
        const int j0 = g * 8;
        #pragma unroll
        for (int jj = 0; jj < 8; jj++) {
            int j = j0 + jj;
            float h = dc[j];
            #pragma unroll
            for (int i = 0; i < 15; i++)
                h = fmaf(fea[i], wc1s[(27+i)*64 + j], h);
            h = fmaxf(h, 0.f);
            a0 = fmaf(h, wc2s[j*3+0], a0);
            a1 = fmaf(h, wc2s[j*3+1], a1);
            a2 = fmaf(h, wc2s[j*3+2], a2);
        }
        if (g > 0) {
            float* cp = cpart + ((g-1)*128 + m)*4;
            cp[0] = a0; cp[1] = a1; cp[2] = a2;
        }
        __syncthreads();
        if (g == 0) {
            #pragma unroll
            for (int gg = 0; gg < 7; gg++) {
                const float* cp = cpart + (gg*128 + m)*4;
                a0 += cp[0]; a1 += cp[1]; a2 += cp[2];
            }
            a0 += bc2s[0]; a1 += bc2s[1]; a2 += bc2s[2];
            float sx = geos[0*132 + m] + b3s[0];
            float sigma = (sx > 20.f) ? sx : log1pf(__expf(sx));
            float alpha = 1.f - __expf(-sigma * dtv);
            comp[m*4+0] = alpha;
            comp[m*4+1] = 1.f / (1.f + __expf(-a0));
            comp[m*4+2] = 1.f / (1.f + __expf(-a1));
            comp[m*4+3] = 1.f / (1.f + __expf(-a2));
        }
    }
    __syncthreads();

    // ---------------- composite: warp-0 parallel scan ----------------
    if (tid < 32) {
        float av[4];
        #pragma unroll
        for (int j = 0; j < 4; j++) av[j] = comp[(lane*4 + j)*4 + 0];
        float q0 = 1.f - av[0] + 1e-10f;
        float q1 = 1.f - av[1] + 1e-10f;
        float q2 = 1.f - av[2] + 1e-10f;
        float q3 = 1.f - av[3] + 1e-10f;
        float inc = ((q0*q1)*(q2*q3));
        #pragma unroll
        for (int off = 1; off < 32; off <<= 1) {
            float t = __shfl_up_sync(0xFFFFFFFF, inc, off);
            if (lane >= off) inc *= t;
        }
        float T = __shfl_up_sync(0xFFFFFFFF, inc, 1);
        if (lane == 0) T = 1.f;
        float wsum = 0.f, dsum = 0.f, r = 0.f, g = 0.f, b = 0.f;
        #pragma unroll
        for (int j = 0; j < 4; j++) {
            int m = lane*4 + j;
            float alpha = av[j];
            float wgt = (T > 1e-4f) ? alpha * T : 0.f;
            wsum += wgt;
            float tsv = near_t + ((float)m + 0.5f) * dtv;
            dsum = fmaf(wgt, tsv, dsum);
            r = fmaf(wgt, comp[m*4+1], r);
            g = fmaf(wgt, comp[m*4+2], g);
            b = fmaf(wgt, comp[m*4+3], b);
            T *= (1.f - alpha + 1e-10f);
        }
        #pragma unroll
        for (int off = 16; off > 0; off >>= 1) {
            wsum += __shfl_xor_sync(0xFFFFFFFF, wsum, off);
            dsum += __shfl_xor_sync(0xFFFFFFFF, dsum, off);
            r    += __shfl_xor_sync(0xFFFFFFFF, r, off);
            g    += __shfl_xor_sync(0xFFFFFFFF, g, off);
            b    += __shfl_xor_sync(0xFFFFFFFF, b, off);
        }
        if (lane == 0) {
            float bgw = 1.f - wsum;
            out[ray*3+0] = r + bgw;
            out[ray*3+1] = g + bgw;
            out[ray*3+2] = b + bgw;
            out[4096*3 + ray] = dsum;
            out[4096*4 + ray] = fminf(fmaxf(wsum, 1e-12f), 1000.f);
        }
    }
}

// ===================== launch =====================
extern "C" void kernel_launch(void* const* d_in, const int* in_sizes, int n_in,
                              void* d_out, int out_size) {
    const float* rays_o = (const float*)d_in[0];
    const float* rays_d = (const float*)d_in[1];
    const float* W1  = (const float*)d_in[2];
    const float* b1  = (const float*)d_in[3];
    const float* W2  = (const float*)d_in[4];
    const float* b2  = (const float*)d_in[5];
    const float* W3  = (const float*)d_in[6];
    const float* b3  = (const float*)d_in[7];
    const float* Wc1 = (const float*)d_in[8];
    const float* bc1 = (const float*)d_in[9];
    const float* Wc2 = (const float*)d_in[10];
    const float* bc2 = (const float*)d_in[11];
    float* out = (float*)d_out;

    prep_pack<<<84, 256>>>(W1, W2, W3);
    cudaFuncSetAttribute(nerf_mma, cudaFuncAttributeMaxDynamicSharedMemorySize, SMEM_BYTES);
    nerf_mma<<<4096, 1024, SMEM_BYTES>>>(rays_o, rays_d, b1, b2, b3,
                                         Wc1, bc1, Wc2, bc2, out);
}

// round 12
// speedup vs baseline: 1.0963x; 1.0963x over previous
#include <cuda_runtime.h>
#include <cuda_bf16.h>
#include <math.h>
#include <stdint.h>

// ===================== asm helpers =====================
__device__ __forceinline__ uint32_t smem_u32(const void* p) {
    uint32_t a;
    asm("{ .reg .u64 t; cvta.to.shared.u64 t, %1; cvt.u32.u64 %0, t; }" : "=r"(a) : "l"(p));
    return a;
}
#define CP16(dst_u32, src_ptr) \
    asm volatile("cp.async.cg.shared.global [%0], [%1], 16;" :: "r"(dst_u32), "l"(src_ptr) : "memory")
#define CP_COMMIT() asm volatile("cp.async.commit_group;" ::: "memory")
#define CP_WAIT(n)  asm volatile("cp.async.wait_group %0;" :: "n"(n) : "memory")

#define MMA(d, a0, a1, a2, a3, b0, b1) \
    asm("mma.sync.aligned.m16n8k16.row.col.f32.bf16.bf16.f32 " \
        "{%0,%1,%2,%3}, {%4,%5,%6,%7}, {%8,%9}, {%0,%1,%2,%3};" \
        : "+f"((d)[0]), "+f"((d)[1]), "+f"((d)[2]), "+f"((d)[3]) \
        : "r"(a0), "r"(a1), "r"(a2), "r"(a3), "r"(b0), "r"(b1))

// ===================== smem layout (persistent) =====================
#define SM_P2    0          // 131072  W2 fragments (resident)
#define SM_P3    131072     // 8192    W3 fragments (resident)
#define SM_ACT   139264     // 65536   per-ray region:
                            //   phase A: P1 (32768) | XF (16384 at +32768)
                            //   phase B: H1F (65536)
                            //   phase C: RED (40960) | GEOS(+40960, 8448) | CPART(+49408,14336) | DIRC(+63744,256)
#define SM_B1    204800     // 1024
#define SM_B2    205824     // 1024
#define SM_B3    206848     // 64
#define SM_DIR   206912     // 128
#define SM_COMP  207040     // 2048
#define SM_BC2   209088     // 16
#define SM_WC1   209104     // 10752 (resident)
#define SM_WC2   219856     // 768
#define SM_BC1   220624     // 256
#define SMEM_BYTES 220880

#define ACT_XF    32768
#define ACT_GEOS  40960
#define ACT_CPART 49408
#define ACT_DIRC  63744

// packed weight image (bf16 fragment order, uint4-paired): P1 32KB | P2 128KB | P3 8KB
__device__ __align__(128) uint32_t g_pack[43008];

__device__ __forceinline__ uint32_t bf16_pack2(float x, float y) {
    __nv_bfloat16 hx = __float2bfloat16(x), hy = __float2bfloat16(y);
    return (uint32_t)__bfloat16_as_ushort(hx) | ((uint32_t)__bfloat16_as_ushort(hy) << 16);
}
__device__ __forceinline__ void sts_bf16(uint32_t addr, float v) {
    uint16_t u = __bfloat16_as_ushort(__float2bfloat16(v));
    asm volatile("st.shared.u16 [%0], %1;" :: "r"(addr), "h"(u));
}
// Cody-Waite reduce to [-pi,pi], then MUFU sin/cos
__device__ __forceinline__ void sincos_fast(float phi, float* s, float* c) {
    float k = rintf(phi * 0.15915494309f);
    float r = fmaf(-k, 6.2831854820251465f, phi);
    r = fmaf(-k, -1.7484556000744263e-07f, r);
    *s = __sinf(r);
    *c = __cosf(r);
}

// byte address (relative) of feature j of sample m inside an A-fragment array
__device__ __forceinline__ uint32_t xf_addr(int m, int j) {
    int p = j >> 1;
    int kt = p >> 3;
    int mtx = m >> 5;
    int lm = m & 31;
    int rb = lm >> 4;
    int l16 = lm & 15;
    int rowbit = l16 >> 3;
    int lane = (l16 & 7) * 4 + (p & 3);
    int jj = ((p >> 2) & 1) * 2 + rowbit;
    return (uint32_t)(((((kt * 4 + mtx) * 2 + rb) * 32 + lane) * 4 + jj) * 4 + (j & 1) * 2);
}

// ===================== prep: pack weights, N-tile pairs per uint4 =====================
__global__ void prep_pack(const float* __restrict__ W1, const float* __restrict__ W2,
                          const float* __restrict__ W3) {
    int s = blockIdx.x * 256 + threadIdx.x;
    if (s >= 21504) return;
    int lane = s & 31;
    int qn = lane >> 2, qk = (lane & 3) * 2;
    const float* W; int kbase, n, ldn, kmax; uint32_t base, idx;
    if (s < 4096) {                       // P1: 4 kt x 32 nt
        int t = s >> 5;
        int kt = t >> 5, nt = t & 31;
        kbase = kt * 16; n = nt * 8 + qn; W = W1; ldn = 256; kmax = 63;
        base = 0; idx = (uint32_t)(((kt * 16 + (nt >> 1)) * 32 + lane) * 4 + (nt & 1) * 2);
    } else if (s < 20480) {               // P2: 16 kt x 32 nt
        int t = (s - 4096) >> 5;
        int kt = t >> 5, nt = t & 31;
        kbase = kt * 16; n = nt * 8 + qn; W = W2; ldn = 256; kmax = 256;
        base = 8192; idx = (uint32_t)(((kt * 16 + (nt >> 1)) * 32 + lane) * 4 + (nt & 1) * 2);
    } else {                              // P3: 16 kt x 2 nt
        int t = (s - 20480) >> 5;
        int kt = t >> 1, nt = t & 1;
        kbase = kt * 16; n = nt * 8 + qn; W = W3; ldn = 16; kmax = 256;
        base = 40960; idx = (uint32_t)((kt * 32 + lane) * 4 + nt * 2);
    }
    int k0 = kbase + qk;
    float e0 = (k0     < kmax) ? W[(k0)     * ldn + n] : 0.f;
    float e1 = (k0 + 1 < kmax) ? W[(k0 + 1) * ldn + n] : 0.f;
    float e2 = (k0 + 8 < kmax) ? W[(k0 + 8) * ldn + n] : 0.f;
    float e3 = (k0 + 9 < kmax) ? W[(k0 + 9) * ldn + n] : 0.f;
    g_pack[base + idx]     = bf16_pack2(e0, e1);
    g_pack[base + idx + 1] = bf16_pack2(e2, e3);
}

// ===================== main kernel: persistent, 148 CTAs x 1024 thr =====================
__global__ void __launch_bounds__(1024, 1)
nerf_mma(const float* __restrict__ rays_o, const float* __restrict__ rays_d,
         const float* __restrict__ b1, const float* __restrict__ b2,
         const float* __restrict__ b3,
         const float* __restrict__ Wc1, const float* __restrict__ bc1,
         const float* __restrict__ Wc2, const float* __restrict__ bc2,
         float* __restrict__ out)
{
    extern __shared__ char smem[];
    const int tid  = threadIdx.x;
    const int lane = tid & 31;
    const int w    = tid >> 5;
    const int mt   = w & 3;               // M-tile (32 rows)
    const int nq   = w >> 2;              // N-eighth (32 cols)
    const int la3  = lane & 3;
    const int qk   = la3 * 2;
    const int r0   = mt * 32 + (lane >> 2);

    const uint32_t sb = smem_u32(smem);
    float* b1s  = (float*)(smem + SM_B1);
    float* b2s  = (float*)(smem + SM_B2);
    float* b3s  = (float*)(smem + SM_B3);
    float* dirs = (float*)(smem + SM_DIR);
    float* comp = (float*)(smem + SM_COMP);
    float* bc2s = (float*)(smem + SM_BC2);
    const uint4* P1q = (const uint4*)(smem + SM_ACT);
    const uint4* P2q = (const uint4*)(smem + SM_P2);
    const uint4* P3q = (const uint4*)(smem + SM_P3);
    const char* gp = (const char*)g_pack;

    // ---- resident staging (once per CTA): P2, P3, color weights ----
    {
        uint32_t d2 = sb + SM_P2, d3 = sb + SM_P3;
        #pragma unroll
        for (int j = 0; j < 8; j++)
            CP16(d2 + (uint32_t)(tid + j * 1024) * 16, gp + 32768 + (tid + j * 1024) * 16);
        if (tid < 512) CP16(d3 + (uint32_t)tid * 16, gp + 163840 + tid * 16);
        if (tid < 672) CP16(sb + SM_WC1 + (uint32_t)tid*16, (const char*)Wc1 + tid*16);
        if (tid < 48)  CP16(sb + SM_WC2 + (uint32_t)tid*16, (const char*)Wc2 + tid*16);
        if (tid < 16)  CP16(sb + SM_BC1 + (uint32_t)tid*16, (const char*)bc1 + tid*16);
        CP_COMMIT();
    }
    if (tid < 256) { b1s[tid] = b1[tid]; b2s[tid] = b2[tid]; }
    if (tid < 16) b3s[tid] = b3[tid];
    if (tid < 3)  bc2s[tid] = bc2[tid];

    for (int ray = blockIdx.x; ray < 4096; ray += gridDim.x) {

        // ---- phase0: stage P1 into ACT (2 x CP16 per thread) ----
        CP16(sb + SM_ACT + (uint32_t)tid * 16,          gp + tid * 16);
        CP16(sb + SM_ACT + (uint32_t)(tid + 1024) * 16, gp + (tid + 1024) * 16);
        CP_COMMIT();

        // ---- ray setup (redundant, all threads) ----
        float ox = rays_o[ray*3+0], oy = rays_o[ray*3+1], oz = rays_o[ray*3+2];
        float rdx = rays_d[ray*3+0], rdy = rays_d[ray*3+1], rdz = rays_d[ray*3+2];
        float inv_norm = rsqrtf(rdx*rdx + rdy*rdy + rdz*rdz);
        float dx = rdx*inv_norm, dy = rdy*inv_norm, dz = rdz*inv_norm;
        float near_t, far_t;
        {
            float dd;
            dd = (fabsf(dx) < 1e-8f) ? 1e-8f : dx; float i0 = __fdividef(1.0f, dd);
            dd = (fabsf(dy) < 1e-8f) ? 1e-8f : dy; float i1 = __fdividef(1.0f, dd);
            dd = (fabsf(dz) < 1e-8f) ? 1e-8f : dz; float i2 = __fdividef(1.0f, dd);
            float t0x=(-1.f-ox)*i0, t1x=(1.f-ox)*i0;
            float t0y=(-1.f-oy)*i1, t1y=(1.f-oy)*i1;
            float t0z=(-1.f-oz)*i2, t1z=(1.f-oz)*i2;
            float nx=fminf(t0x,t1x), fx=fmaxf(t0x,t1x);
            float ny=fminf(t0y,t1y), fy=fmaxf(t0y,t1y);
            float nz=fminf(t0z,t1z), fz=fmaxf(t0z,t1z);
            near_t = fmaxf(fmaxf(nx, fmaxf(ny, nz)), 0.02f);
            far_t  = fminf(fmaxf(fx, fmaxf(fy, fz)), 1000.f);
            far_t  = fmaxf(far_t, near_t + 0.001f);
        }
        const float dtv = (far_t - near_t) * (1.0f/128.0f);

        // ---- posenc (8-way split over g = tid>>7) -> XF fragments ----
        {
            const int m = tid & 127, g = tid >> 7;
            float t = near_t + ((float)m + 0.5f) * dtv;
            float px = ox + t*dx, py = oy + t*dy, pz = oz + t*dz;
            const uint32_t xbase = sb + SM_ACT + ACT_XF;
            if (g < 6) {
                int ci = g >> 1, half = g & 1;
                float pv = (ci == 0) ? px : ((ci == 1) ? py : pz);
                float f = half ? 32.f : 1.f;
                #pragma unroll
                for (int q = 0; q < 5; q++) {
                    int qq = half*5 + q;
                    float s, c;
                    sincos_fast(pv * f, &s, &c);
                    sts_bf16(xbase + xf_addr(m, 3 + ci*10 + qq), s);
                    sts_bf16(xbase + xf_addr(m, 33 + ci*10 + qq), c);
                    f *= 2.f;
                }
            } else if (g == 6) {
                sts_bf16(xbase + xf_addr(m, 0), px);
                sts_bf16(xbase + xf_addr(m, 1), py);
                sts_bf16(xbase + xf_addr(m, 2), pz);
                sts_bf16(xbase + xf_addr(m, 63), 0.f);
            } else {
                if (m < 27) {
                    int j = m;
                    float dv[3] = {dx, dy, dz};
                    float v;
                    if (j < 3) v = dv[j];
                    else if (j < 15) { int jj = j-3;  float s,c; sincos_fast(dv[jj>>2]*(float)(1<<(jj&3)), &s, &c); v = s; }
                    else             { int jj = j-15; float s,c; sincos_fast(dv[jj>>2]*(float)(1<<(jj&3)), &s, &c); v = c; }
                    dirs[j] = v;
                }
            }
        }

        CP_WAIT(0);
        __syncthreads();

        // ---------------- Layer 1 ----------------
        float acc[2][4][4];
        #pragma unroll
        for (int rb = 0; rb < 2; rb++)
            #pragma unroll
            for (int ct = 0; ct < 4; ct++)
                #pragma unroll
                for (int j = 0; j < 4; j++) acc[rb][ct][j] = 0.f;

        {
            const uint4* pA = (const uint4*)(smem + SM_ACT + ACT_XF) + mt*64 + lane;
            #pragma unroll
            for (int kt = 0; kt < 4; kt++) {
                uint4 a0 = pA[kt*256];
                uint4 a1 = pA[kt*256 + 32];
                uint4 p0 = P1q[(kt*16 + nq*2)*32 + lane];
                uint4 p1 = P1q[(kt*16 + nq*2 + 1)*32 + lane];
                MMA(acc[0][0], a0.x, a0.y, a0.z, a0.w, p0.x, p0.y);
                MMA(acc[0][1], a0.x, a0.y, a0.z, a0.w, p0.z, p0.w);
                MMA(acc[0][2], a0.x, a0.y, a0.z, a0.w, p1.x, p1.y);
                MMA(acc[0][3], a0.x, a0.y, a0.z, a0.w, p1.z, p1.w);
                MMA(acc[1][0], a1.x, a1.y, a1.z, a1.w, p0.x, p0.y);
                MMA(acc[1][1], a1.x, a1.y, a1.z, a1.w, p0.z, p0.w);
                MMA(acc[1][2], a1.x, a1.y, a1.z, a1.w, p1.x, p1.y);
                MMA(acc[1][3], a1.x, a1.y, a1.z, a1.w, p1.z, p1.w);
            }
        }
        __syncthreads();       // everyone done reading XF / P1

        // epilogue: H1 = relu(acc + b1) -> A-fragment layout (overwrites ACT)
        #pragma unroll
        for (int ct = 0; ct < 4; ct++) {
            int n0 = nq*32 + ct*8 + qk;
            float2 bb = *(const float2*)(b1s + n0);
            int kt = nq*2 + (ct >> 1);
            int j0 = (ct & 1) * 2;
            #pragma unroll
            for (int rb = 0; rb < 2; rb++) {
                uint32_t v0 = bf16_pack2(fmaxf(acc[rb][ct][0] + bb.x, 0.f), fmaxf(acc[rb][ct][1] + bb.y, 0.f));
                uint32_t v1 = bf16_pack2(fmaxf(acc[rb][ct][2] + bb.x, 0.f), fmaxf(acc[rb][ct][3] + bb.y, 0.f));
                uint32_t idx = (uint32_t)((((kt*4 + mt)*2 + rb)*32 + lane)*4 + j0);
                *(uint2*)(smem + SM_ACT + idx*4) = make_uint2(v0, v1);
            }
        }
        __syncthreads();

        // ---------------- Layer 2: 16 K-tiles ----------------
        #pragma unroll
        for (int rb = 0; rb < 2; rb++)
            #pragma unroll
            for (int ct = 0; ct < 4; ct++)
                #pragma unroll
                for (int j = 0; j < 4; j++) acc[rb][ct][j] = 0.f;

        {
            const uint4* pA = (const uint4*)(smem + SM_ACT) + mt*64 + lane;
            #pragma unroll
            for (int kt = 0; kt < 16; kt++) {
                uint4 a0 = pA[kt*256];
                uint4 a1 = pA[kt*256 + 32];
                uint4 p0 = P2q[(kt*16 + nq*2)*32 + lane];
                uint4 p1 = P2q[(kt*16 + nq*2 + 1)*32 + lane];
                MMA(acc[0][0], a0.x, a0.y, a0.z, a0.w, p0.x, p0.y);
                MMA(acc[0][1], a0.x, a0.y, a0.z, a0.w, p0.z, p0.w);
                MMA(acc[0][2], a0.x, a0.y, a0.z, a0.w, p1.x, p1.y);
                MMA(acc[0][3], a0.x, a0.y, a0.z, a0.w, p1.z, p1.w);
                MMA(acc[1][0], a1.x, a1.y, a1.z, a1.w, p0.x, p0.y);
                MMA(acc[1][1], a1.x, a1.y, a1.z, a1.w, p0.z, p0.w);
                MMA(acc[1][2], a1.x, a1.y, a1.z, a1.w, p1.x, p1.y);
                MMA(acc[1][3], a1.x, a1.y, a1.z, a1.w, p1.z, p1.w);
            }
        }
        __syncthreads();       // H1F reads done; ACT scratch may be reused

        // ---------------- Layer 3 ----------------
        float geo[2][2][4];
        #pragma unroll
        for (int rb = 0; rb < 2; rb++)
            #pragma unroll
            for (int nt = 0; nt < 2; nt++)
                #pragma unroll
                for (int j = 0; j < 4; j++) geo[rb][nt][j] = 0.f;

        #pragma unroll
        for (int ii = 0; ii < 2; ii++) {
            int kt3 = nq*2 + ii;
            uint4 bq = P3q[kt3*32 + lane];
            int n0 = nq*32 + (2*ii)*8 + qk;
            float2 bb0 = *(const float2*)(b2s + n0);
            float2 bb1 = *(const float2*)(b2s + n0 + 8);
            #pragma unroll
            for (int rb = 0; rb < 2; rb++) {
                uint32_t a0 = bf16_pack2(fmaxf(acc[rb][2*ii][0] + bb0.x, 0.f),  fmaxf(acc[rb][2*ii][1] + bb0.y, 0.f));
                uint32_t a1 = bf16_pack2(fmaxf(acc[rb][2*ii][2] + bb0.x, 0.f),  fmaxf(acc[rb][2*ii][3] + bb0.y, 0.f));
                uint32_t a2 = bf16_pack2(fmaxf(acc[rb][2*ii+1][0] + bb1.x, 0.f), fmaxf(acc[rb][2*ii+1][1] + bb1.y, 0.f));
                uint32_t a3 = bf16_pack2(fmaxf(acc[rb][2*ii+1][2] + bb1.x, 0.f), fmaxf(acc[rb][2*ii+1][3] + bb1.y, 0.f));
                MMA(geo[rb][0], a0, a1, a2, a3, bq.x, bq.y);
                MMA(geo[rb][1], a0, a1, a2, a3, bq.z, bq.w);
            }
        }

        // K reduction: groups 1-4 write 4 buffers; groups 5-7 add; nq0 finalizes
        float* redbase = (float*)(smem + SM_ACT);
        if (nq >= 1 && nq <= 4) {
            float* red = redbase + (nq - 1) * 2560;
            #pragma unroll
            for (int rb = 0; rb < 2; rb++)
                #pragma unroll
                for (int nt = 0; nt < 2; nt++) {
                    int c = nt*8 + qk;
                    int rr = r0 + rb*16;
                    red[rr*20 + c]       = geo[rb][nt][0];
                    red[rr*20 + c + 1]   = geo[rb][nt][1];
                    red[(rr+8)*20 + c]   = geo[rb][nt][2];
                    red[(rr+8)*20 + c+1] = geo[rb][nt][3];
                }
        }
        __syncthreads();
        if (nq >= 5) {
            float* red = redbase + (nq - 5) * 2560;
            #pragma unroll
            for (int rb = 0; rb < 2; rb++)
                #pragma unroll
                for (int nt = 0; nt < 2; nt++) {
                    int c = nt*8 + qk;
                    int rr = r0 + rb*16;
                    red[rr*20 + c]       += geo[rb][nt][0];
                    red[rr*20 + c + 1]   += geo[rb][nt][1];
                    red[(rr+8)*20 + c]   += geo[rb][nt][2];
                    red[(rr+8)*20 + c+1] += geo[rb][nt][3];
                }
        }
        __syncthreads();
        if (nq == 0) {
            float* geos = (float*)(smem + SM_ACT + ACT_GEOS);   // [16][132] transposed
            #pragma unroll
            for (int rb = 0; rb < 2; rb++)
                #pragma unroll
                for (int nt = 0; nt < 2; nt++) {
                    int c = nt*8 + qk;
                    #pragma unroll
                    for (int hv = 0; hv < 2; hv++) {
                        int rr = r0 + rb*16 + hv*8;
                        float v0 = geo[rb][nt][2*hv+0];
                        float v1 = geo[rb][nt][2*hv+1];
                        #pragma unroll
                        for (int gg = 0; gg < 4; gg++) {
                            v0 += redbase[gg*2560 + rr*20 + c];
                            v1 += redbase[gg*2560 + rr*20 + c + 1];
                        }
                        geos[c*132 + rr]     = v0;
                        geos[(c+1)*132 + rr] = v1;
                    }
                }
        }
        __syncthreads();

        // ---------------- color head ----------------
        {
            const float* wc1s = (const float*)(smem + SM_WC1);
            const float* wc2s = (const float*)(smem + SM_WC2);
            const float* bc1s = (const float*)(smem + SM_BC1);
            const float* geos = (const float*)(smem + SM_ACT + ACT_GEOS);
            float* dc   = (float*)(smem + SM_ACT + ACT_DIRC);
            float* cpart= (float*)(smem + SM_ACT + ACT_CPART);

            if (tid < 64) {
                int j = tid;
                float h = bc1s[j];
                #pragma unroll
                for (int i = 0; i < 27; i++)
                    h = fmaf(dirs[i], wc1s[i*64 + j], h);
                dc[j] = h;
            }
            __syncthreads();

            const int m = tid & 127, g = tid >> 7;
            float fea[15];
            #pragma unroll
            for (int i = 0; i < 15; i++) fea[i] = geos[(1+i)*132 + m] + b3s[1+i];
            float a0 = 0.f, a1 = 0.f, a2 = 0.f;
            const int j0 = g * 8;
            #pragma unroll
            for (int jj = 0; jj < 8; jj++) {
                int j = j0 + jj;
                float h = dc[j];
                #pragma unroll
                for (int i = 0; i < 15; i++)
                    h = fmaf(fea[i], wc1s[(27+i)*64 + j], h);
                h = fmaxf(h, 0.f);
                a0 = fmaf(h, wc2s[j*3+0], a0);
                a1 = fmaf(h, wc2s[j*3+1], a1);
                a2 = fmaf(h, wc2s[j*3+2], a2);
            }
            if (g > 0) {
                float* cp = cpart + ((g-1)*128 + m)*4;
                cp[0] = a0; cp[1] = a1; cp[2] = a2;
            }
            __syncthreads();
            if (g == 0) {
                #pragma unroll
                for (int gg = 0; gg < 7; gg++) {
                    const float* cp = cpart + (gg*128 + m)*4;
                    a0 += cp[0]; a1 += cp[1]; a2 += cp[2];
                }
                a0 += bc2s[0]; a1 += bc2s[1]; a2 += bc2s[2];
                float sx = geos[0*132 + m] + b3s[0];
                float sigma = (sx > 20.f) ? sx : log1pf(__expf(sx));
                float alpha = 1.f - __expf(-sigma * dtv);
                comp[m*4+0] = alpha;
                comp[m*4+1] = 1.f / (1.f + __expf(-a0));
                comp[m*4+2] = 1.f / (1.f + __expf(-a1));
                comp[m*4+3] = 1.f / (1.f + __expf(-a2));
            }
        }
        __syncthreads();

        // ---------------- composite: warp-0 parallel scan ----------------
        if (tid < 32) {
            float av[4];
            #pragma unroll
            for (int j = 0; j < 4; j++) av[j] = comp[(lane*4 + j)*4 + 0];
            float q0 = 1.f - av[0] + 1e-10f;
            float q1 = 1.f - av[1] + 1e-10f;
            float q2 = 1.f - av[2] + 1e-10f;
            float q3 = 1.f - av[3] + 1e-10f;
            float inc = ((q0*q1)*(q2*q3));
            #pragma unroll
            for (int off = 1; off < 32; off <<= 1) {
                float t = __shfl_up_sync(0xFFFFFFFF, inc, off);
                if (lane >= off) inc *= t;
            }
            float T = __shfl_up_sync(0xFFFFFFFF, inc, 1);
            if (lane == 0) T = 1.f;
            float wsum = 0.f, dsum = 0.f, r = 0.f, g = 0.f, b = 0.f;
            #pragma unroll
            for (int j = 0; j < 4; j++) {
                int m = lane*4 + j;
                float alpha = av[j];
                float wgt = (T > 1e-4f) ? alpha * T : 0.f;
                wsum += wgt;
                float tsv = near_t + ((float)m + 0.5f) * dtv;
                dsum = fmaf(wgt, tsv, dsum);
                r = fmaf(wgt, comp[m*4+1], r);
                g = fmaf(wgt, comp[m*4+2], g);
                b = fmaf(wgt, comp[m*4+3], b);
                T *= (1.f - alpha + 1e-10f);
            }
            #pragma unroll
            for (int off = 16; off > 0; off >>= 1) {
                wsum += __shfl_xor_sync(0xFFFFFFFF, wsum, off);
                dsum += __shfl_xor_sync(0xFFFFFFFF, dsum, off);
                r    += __shfl_xor_sync(0xFFFFFFFF, r, off);
                g    += __shfl_xor_sync(0xFFFFFFFF, g, off);
                b    += __shfl_xor_sync(0xFFFFFFFF, b, off);
            }
            if (lane == 0) {
                float bgw = 1.f - wsum;
                out[ray*3+0] = r + bgw;
                out[ray*3+1] = g + bgw;
                out[ray*3+2] = b + bgw;
                out[4096*3 + ray] = dsum;
                out[4096*4 + ray] = fminf(fmaxf(wsum, 1e-12f), 1000.f);
            }
        }
        __syncthreads();   // comp reads done before next ray's color phase reuses it
    }
}

// ===================== launch =====================
extern "C" void kernel_launch(void* const* d_in, const int* in_sizes, int n_in,
                              void* d_out, int out_size) {
    const float* rays_o = (const float*)d_in[0];
    const float* rays_d = (const float*)d_in[1];
    const float* W1  = (const float*)d_in[2];
    const float* b1  = (const float*)d_in[3];
    const float* W2  = (const float*)d_in[4];
    const float* b2  = (const float*)d_in[5];
    const float* W3  = (const float*)d_in[6];
    const float* b3  = (const float*)d_in[7];
    const float* Wc1 = (const float*)d_in[8];
    const float* bc1 = (const float*)d_in[9];
    const float* Wc2 = (const float*)d_in[10];
    const float* bc2 = (const float*)d_in[11];
    float* out = (float*)d_out;

    prep_pack<<<84, 256>>>(W1, W2, W3);
    cudaFuncSetAttribute(nerf_mma, cudaFuncAttributeMaxDynamicSharedMemorySize, SMEM_BYTES);
    nerf_mma<<<148, 1024, SMEM_BYTES>>>(rays_o, rays_d, b1, b2, b3,
                                        Wc1, bc1, Wc2, bc2, out);
}